// round 7
// baseline (speedup 1.0000x reference)
#include <cuda_runtime.h>
#include <cuda_bf16.h>
#include <math.h>

// ---------------- problem constants ----------------
#define BB   4
#define CF   512
#define KC   19
#define NT   1024            // tokens per image (32x32)
#define IMG  512
#define PPX  256             // patch pixels (16x16)
#define TK   (2*KC)          // 38
#define NBLK 38              // chain kernel blocks

// output layout (floats): sfc, tfc, slc, tlc, s_proto, t_proto
#define SZ_FC    ((size_t)BB*NT*CF)
#define OFF_SFC  0ULL
#define OFF_TFC  (SZ_FC)
#define OFF_SLC  (2*SZ_FC)
#define SZ_LC    ((size_t)BB*KC*PPX*NT)
#define OFF_TLC  (OFF_SLC + SZ_LC)
#define OFF_SP   (OFF_TLC + SZ_LC)

// k_back block counts
#define NLC  (8 * (KC*16) * (BB*2))        // 19456 labelcorr blocks
#define NFC  ((NT/2) * 2 * BB)             // 4096 featcorr blocks (2 tokens each)

// ---------------- device scratch (static; no allocation) ----------------
__device__ float g_stok[BB*NT*CF];                 // [b][n][c]
__device__ float g_ttok[BB*NT*CF];
__device__ int           g_mode[2*BB*NT];          // [t][b][n]
__device__ unsigned char g_pure[2*BB*NT];
__device__ int   g_clist[BB*TK*NT];                // [(b*2+t)*KC+k][i]
__device__ int   g_ccnt [BB*TK];
__device__ int   g_rank [BB*2*NT];
__device__ int   g_gate [BB*2];
__device__ float g_proto[TK*CF];                   // final proto state
__device__ int   g_order[BB*TK*NT];
__device__ int           g_src  [2*BB*NT];
__device__ unsigned char g_apply[2*BB*NT];
__device__ float g_statmean[BB*2*CF];
__device__ float g_statstd [BB*2*CF];
__device__ int   g_both[BB];

// software grid barrier state
__device__ unsigned g_barGen = 0;
__device__ unsigned g_barCnt = 0;

__device__ __forceinline__ void grid_bar() {
    __threadfence();
    __syncthreads();
    if (threadIdx.x == 0) {
        unsigned my = *((volatile unsigned*)&g_barGen);
        unsigned a = atomicAdd(&g_barCnt, 1u);
        if (a == NBLK - 1) {
            atomicExch(&g_barCnt, 0u);
            __threadfence();
            atomicExch(&g_barGen, my + 1u);
        } else {
            while (*((volatile unsigned*)&g_barGen) == my) { __nanosleep(64); }
        }
        __threadfence();
    }
    __syncthreads();
}

// ================= k_front: patch stats + upsample (merged) =================
// blocks [0, 2048): patch; blocks [2048, 2304): upsample. 256 threads.
__global__ void __launch_bounds__(256) k_front(const int* __restrict__ slab,
                                               const float* __restrict__ tp,
                                               const float* __restrict__ sfeat,
                                               const float* __restrict__ tfeat) {
    int tid = threadIdx.x;
    if (blockIdx.x < 2048) {
        int id = blockIdx.x;
        int z = id >> 10;            // 0 source, 1 target
        int rem = id & 1023;
        int b = rem >> 8;
        int px = rem & 255;          // patch group (4 patches)
        int p = tid >> 6, r = tid & 63;
        int pi = r >> 2, xq = r & 3;
        int n = px * 4 + p;
        int y = (n >> 5) * 16 + pi;
        int xb = (n & 31) * 16 + xq * 4;
        __shared__ int h[4][20];
        if (tid < 80) h[tid / 20][tid % 20] = 0;
        if (z == 0) {
            const int4* s4 = (const int4*)slab;
            int4 v = s4[((size_t)b * IMG + y) * (IMG/4) + (xb >> 2)];
            __syncthreads();
            atomicAdd(&h[p][v.x + 1], 1); atomicAdd(&h[p][v.y + 1], 1);
            atomicAdd(&h[p][v.z + 1], 1); atomicAdd(&h[p][v.w + 1], 1);
            __syncthreads();
            if (r == 0) {
                int best = -1, mj = 0;
                for (int j = 0; j < 20; j++) if (h[p][j] > best) { best = h[p][j]; mj = j; }
                int mode = mj - 1;
                int nvalid = 256 - h[p][0];
                int agree = (mode >= 0) ? h[p][mj] : 0;
                float purity = (float)agree / (float)(nvalid > 0 ? nvalid : 1);
                g_mode[b * NT + n] = mode;
                g_pure[b * NT + n] = (unsigned char)((purity >= 0.9f) && (nvalid > 0));
            }
        } else {
            const float4* tp4 = (const float4*)tp;
            size_t pix4 = (((size_t)b * KC) * IMG + y) * (IMG/4) + (xb >> 2);
            float mv0=-1.f, mv1=-1.f, mv2=-1.f, mv3=-1.f;
            int mk0=0, mk1=0, mk2=0, mk3=0;
#pragma unroll
            for (int k = 0; k < KC; k++) {
                float4 v = tp4[pix4 + (size_t)k * (IMG * (IMG/4))];
                if (v.x > mv0) { mv0 = v.x; mk0 = k; }
                if (v.y > mv1) { mv1 = v.y; mk1 = k; }
                if (v.z > mv2) { mv2 = v.z; mk2 = k; }
                if (v.w > mv3) { mv3 = v.w; mk3 = k; }
            }
            __shared__ float sc[256];
            sc[tid] = mv0 + mv1 + mv2 + mv3;
            __syncthreads();
            int l0 = (mv0 < 0.9f) ? 0 : mk0 + 1;
            int l1 = (mv1 < 0.9f) ? 0 : mk1 + 1;
            int l2 = (mv2 < 0.9f) ? 0 : mk2 + 1;
            int l3 = (mv3 < 0.9f) ? 0 : mk3 + 1;
            atomicAdd(&h[p][l0], 1); atomicAdd(&h[p][l1], 1);
            atomicAdd(&h[p][l2], 1); atomicAdd(&h[p][l3], 1);
            __syncthreads();
            for (int s = 32; s > 0; s >>= 1) {
                if (r < s) sc[tid] += sc[tid + s];
                __syncthreads();
            }
            if (r == 0) {
                float cmean = sc[p * 64] / 256.f;
                int best = -1, mj = 0;
                for (int j = 0; j < 20; j++) if (h[p][j] > best) { best = h[p][j]; mj = j; }
                int mode = mj - 1;
                int nvalid = 256 - h[p][0];
                int agree = (mode >= 0) ? h[p][mj] : 0;
                float purity = (float)agree / (float)(nvalid > 0 ? nvalid : 1);
                int pure = (purity >= 0.9f) && (nvalid > 0) && (cmean >= 0.9f);
                g_mode[BB*NT + b * NT + n] = mode;
                g_pure[BB*NT + b * NT + n] = (unsigned char)pure;
            }
        }
    } else {
        // upsample: 2x bilinear (jax semantics); 2 channels per thread
        int u = blockIdx.x - 2048;
        int yo = u & 31;
        int b = (u >> 5) & 3;
        int t = u >> 7;
        const float* in = t ? tfeat : sfeat;
        float* dst = t ? g_ttok : g_stok;
        int k = yo >> 1; int r0, r1; float wy0, wy1;
        if (yo & 1) { r0 = k; r1 = (k < 15) ? k + 1 : 15; wy0 = 0.75f; wy1 = 0.25f; }
        else        { r0 = (k > 0) ? k - 1 : 0; r1 = k;   wy0 = 0.25f; wy1 = 0.75f; }
#pragma unroll
        for (int half = 0; half < 2; half++) {
            int c = tid + half * 256;
            const float4* base = (const float4*)(in + ((size_t)b * CF + c) * 256);
            float a0[16], a1[16];
#pragma unroll
            for (int q = 0; q < 4; q++) {
                float4 v0 = base[r0*4 + q], v1 = base[r1*4 + q];
                a0[q*4+0]=v0.x; a0[q*4+1]=v0.y; a0[q*4+2]=v0.z; a0[q*4+3]=v0.w;
                a1[q*4+0]=v1.x; a1[q*4+1]=v1.y; a1[q*4+2]=v1.z; a1[q*4+3]=v1.w;
            }
#pragma unroll
            for (int xo = 0; xo < 32; xo++) {
                int kx = xo >> 1; int x0, x1; float wx0, wx1;
                if (xo & 1) { x0 = kx; x1 = (kx < 15) ? kx + 1 : 15; wx0 = 0.75f; wx1 = 0.25f; }
                else        { x0 = (kx > 0) ? kx - 1 : 0; x1 = kx;   wx0 = 0.25f; wx1 = 0.75f; }
                float v0 = wy0 * a0[x0] + wy1 * a1[x0];
                float v1 = wy0 * a0[x1] + wy1 * a1[x1];
                dst[((size_t)b * NT + yo*32 + xo) * CF + c] = wx0 * v0 + wx1 * v1;
            }
        }
    }
}

// ============ k_chain: prep+stats -> (means+EMA+dist+sort) -> match =========
// 38 blocks x 1024 threads, two grid barriers.
__global__ void __launch_bounds__(1024) k_chain() {
    __shared__ int   lst[NT];
    __shared__ float ds[NT];
    __shared__ float4 pr4[128];
    __shared__ float4 part4[8][128];
    __shared__ int simp[2][NT];
    __shared__ int simpcnt[2];
    int tid = threadIdx.x;
    int w = tid >> 5, lane = tid & 31;

    // ---------------- phase A: blocks 0..3 do prep + impure stats for b ----
    if (blockIdx.x < BB) {
        int b = blockIdx.x;
        for (int item = w; item < 40; item += 32) {
            if (item < TK) {
                int t = item / KC, k = item % KC;
                const int* md = g_mode + t * BB * NT + b * NT;
                const unsigned char* pu = g_pure + t * BB * NT + b * NT;
                int cnt = 0;
                for (int base = 0; base < NT; base += 32) {
                    int n = base + lane;
                    bool mem = pu[n] && (md[n] == k);
                    unsigned m = __ballot_sync(0xffffffffu, mem);
                    int pos = cnt + __popc(m & ((1u << lane) - 1u));
                    if (mem) {
                        g_clist[((b*2+t)*KC + k)*NT + pos] = n;
                        g_rank[(b*2+t)*NT + n] = pos;
                    }
                    cnt += __popc(m);
                }
                if (lane == 0) g_ccnt[(b*2+t)*KC + k] = cnt;
            } else {
                int t = item - TK;
                const unsigned char* pu = g_pure + t * BB * NT + b * NT;
                int cnt = 0;
                for (int base = 0; base < NT; base += 32) {
                    int n = base + lane;
                    bool mem = !pu[n];
                    unsigned m = __ballot_sync(0xffffffffu, mem);
                    int pos = cnt + __popc(m & ((1u << lane) - 1u));
                    if (mem) simp[t][pos] = n;
                    cnt += __popc(m);
                }
                if (lane == 0) simpcnt[t] = cnt;
            }
        }
        __syncthreads();
        if (tid < 2) {
            int s = 0;
            for (int k = 0; k < KC; k++) s += g_ccnt[(b*2+tid)*KC + k];
            g_gate[b*2+tid] = (s > 0);
        }
        if (tid == 0) g_both[b] = (simpcnt[0] > 0) && (simpcnt[1] > 0);
        // impure stats: 2 tensors x 4 member-lanes x 128 c4
        int t = tid >> 9, rr = tid & 511;
        int l = rr >> 7, c4 = rr & 127;
        int n = simpcnt[t];
        const float4* f4 = (const float4*)((t ? g_ttok : g_stok) + (size_t)b * NT * CF);
        float4 a = make_float4(0.f, 0.f, 0.f, 0.f);
        int i = l;
        for (; i + 4 < n; i += 8) {
            float4 v0 = f4[(size_t)simp[t][i    ] * 128 + c4];
            float4 v1 = f4[(size_t)simp[t][i + 4] * 128 + c4];
            a.x += v0.x + v1.x; a.y += v0.y + v1.y; a.z += v0.z + v1.z; a.w += v0.w + v1.w;
        }
        for (; i < n; i += 4) {
            float4 v = f4[(size_t)simp[t][i] * 128 + c4];
            a.x += v.x; a.y += v.y; a.z += v.z; a.w += v.w;
        }
        part4[l + (t ? 4 : 0)][c4] = a;
        __syncthreads();
        float4 mn;
        {
            int tt = tid >> 9;
            if ((tid & 511) < 128) {
                int cc4 = tid & 127;
                float4 s0 = part4[tt*4+0][cc4], s1 = part4[tt*4+1][cc4];
                float4 s2 = part4[tt*4+2][cc4], s3 = part4[tt*4+3][cc4];
                int nn = simpcnt[tt];
                float inv = 1.f / (float)(nn > 0 ? nn : 1);
                mn.x = (s0.x + s1.x + s2.x + s3.x) * inv;
                mn.y = (s0.y + s1.y + s2.y + s3.y) * inv;
                mn.z = (s0.z + s1.z + s2.z + s3.z) * inv;
                mn.w = (s0.w + s1.w + s2.w + s3.w) * inv;
                ((float4*)(g_statmean + (b * 2 + tt) * CF))[cc4] = mn;
                pr4[cc4 + 0] = (tt == 0) ? mn : pr4[cc4];     // dummy keep
            }
        }
        __syncthreads();
        // broadcast mean through smem for variance pass
        __shared__ float4 smean2[2][128];
        if ((tid & 511) < 128) smean2[tid >> 9][tid & 127] = ((float4*)(g_statmean + (b * 2 + (tid >> 9)) * CF))[tid & 127];
        __syncthreads();
        float4 mnv = smean2[t][c4];
        float4 q = make_float4(0.f, 0.f, 0.f, 0.f);
        for (i = l; i < n; i += 4) {
            float4 v = f4[(size_t)simp[t][i] * 128 + c4];
            float dx = v.x - mnv.x, dy = v.y - mnv.y, dz = v.z - mnv.z, dw = v.w - mnv.w;
            q.x += dx*dx; q.y += dy*dy; q.z += dz*dz; q.w += dw*dw;
        }
        part4[l + (t ? 4 : 0)][c4] = q;
        __syncthreads();
        if ((tid & 511) < 128) {
            int tt = tid >> 9, cc4 = tid & 127;
            float4 s0 = part4[tt*4+0][cc4], s1 = part4[tt*4+1][cc4];
            float4 s2 = part4[tt*4+2][cc4], s3 = part4[tt*4+3][cc4];
            int nn = simpcnt[tt];
            float invv = 1.f / (float)(nn - 1 > 0 ? nn - 1 : 1);
            float4 sd;
            sd.x = (nn > 1) ? sqrtf((s0.x + s1.x + s2.x + s3.x) * invv) : 0.f;
            sd.y = (nn > 1) ? sqrtf((s0.y + s1.y + s2.y + s3.y) * invv) : 0.f;
            sd.z = (nn > 1) ? sqrtf((s0.z + s1.z + s2.z + s3.z) * invv) : 0.f;
            sd.w = (nn > 1) ? sqrtf((s0.w + s1.w + s2.w + s3.w) * invv) : 0.f;
            ((float4*)(g_statstd + (b * 2 + tt) * CF))[cc4] = sd;
        }
    }
    grid_bar();

    // ---------------- phase B: per-class means + EMA + dist + sort ---------
    {
        int bid = blockIdx.x;            // t*KC + k
        int t = bid / KC, k = bid - t * KC;
        int l = tid >> 7, c4 = tid & 127;
        float4 pv = make_float4(0.f, 0.f, 0.f, 0.f);   // valid for tid<128
        int gate0[BB], gate1[BB];
#pragma unroll
        for (int b = 0; b < BB; b++) { gate0[b] = __ldcg(&g_gate[b*2]); gate1[b] = __ldcg(&g_gate[b*2+1]); }
        const float4* f4 = (const float4*)((t ? g_ttok : g_stok));
#pragma unroll
        for (int b = 0; b < BB; b++) {
            int cnt = __ldcg(&g_ccnt[b*TK + bid]);
            for (int i = tid; i < cnt; i += 1024) lst[i] = __ldcg(&g_clist[(b*TK + bid)*NT + i]);
            __syncthreads();
            const float4* fb = f4 + (size_t)b * NT * 128;
            float4 a = make_float4(0.f, 0.f, 0.f, 0.f);
            int i = l;
            for (; i + 8 < cnt; i += 16) {
                float4 v0 = fb[(size_t)lst[i    ] * 128 + c4];
                float4 v1 = fb[(size_t)lst[i + 8] * 128 + c4];
                a.x += v0.x + v1.x; a.y += v0.y + v1.y; a.z += v0.z + v1.z; a.w += v0.w + v1.w;
            }
            for (; i < cnt; i += 8) {
                float4 v = fb[(size_t)lst[i] * 128 + c4];
                a.x += v.x; a.y += v.y; a.z += v.z; a.w += v.w;
            }
            part4[l][c4] = a;
            __syncthreads();
            if (tid < 128) {
                float4 s = part4[0][c4];
#pragma unroll
                for (int j = 1; j < 8; j++) {
                    float4 p = part4[j][c4];
                    s.x += p.x; s.y += p.y; s.z += p.z; s.w += p.w;
                }
                float inv = 1.f / (float)(cnt > 0 ? cnt : 1);
                int gate = t ? (gate0[b] && gate1[b]) : gate0[b];
                if (gate && cnt > 0) {
                    pv.x = 0.99f*pv.x + 0.01f*(s.x*inv);
                    pv.y = 0.99f*pv.y + 0.01f*(s.y*inv);
                    pv.z = 0.99f*pv.z + 0.01f*(s.z*inv);
                    pv.w = 0.99f*pv.w + 0.01f*(s.w*inv);
                }
                pr4[c4] = pv;
            }
            __syncthreads();
            // distances: 32 warps over members
            for (int mi = w; mi < cnt; mi += 32) {
                const float4* fv = fb + (size_t)lst[mi] * 128;
                float acc = 0.f;
#pragma unroll
                for (int q = 0; q < 4; q++) {
                    int e = lane + q * 32;
                    float4 v = fv[e];
                    float4 p = pr4[e];
                    float d0 = v.x - p.x, d1 = v.y - p.y, d2 = v.z - p.z, d3 = v.w - p.w;
                    acc += d0*d0 + d1*d1 + d2*d2 + d3*d3;
                }
                for (int o = 16; o; o >>= 1) acc += __shfl_down_sync(0xffffffffu, acc, o);
                if (lane == 0) ds[mi] = sqrtf(acc);
            }
            __syncthreads();
            int lid = (b*2+t)*KC + k;
            for (int i2 = tid; i2 < cnt; i2 += 1024) {
                float di = ds[i2]; int r = 0;
                for (int j = 0; j < cnt; j++) {
                    float dj = ds[j];
                    r += (dj < di) || (dj == di && j < i2);
                }
                g_order[lid * NT + r] = lst[i2];
            }
            __syncthreads();
        }
        if (tid < 128) ((float4*)g_proto)[bid * 128 + c4] = pv;
    }
    grid_bar();

    // ---------------- phase C: cyclic source matching -----------------------
    {
        int id = blockIdx.x * 1024 + tid;
        if (id < 2 * BB * NT) {
            int b = id >> 11;
            int rem = id & 2047;
            int t = rem >> 10;
            int n = rem & 1023;
            int gate_st = __ldcg(&g_gate[b*2]) && __ldcg(&g_gate[b*2+1]);
            int mode = g_mode[t * BB * NT + b * NT + n];
            int pure = g_pure[t * BB * NT + b * NT + n];
            int cm = mode > 0 ? mode : 0;
            int cs = __ldcg(&g_ccnt[b*TK + (1 - t) * KC + cm]);
            int apply = pure && (cs > 0) && gate_st;
            int src = 0;
            if (apply) {
                int r = __ldcg(&g_rank[(b*2 + t) * NT + n]);
                src = __ldcg(&g_order[(((b*2 + (1 - t)) * KC + cm)) * NT + (r % cs)]);
            }
            g_src  [(t * BB + b) * NT + n] = src;
            g_apply[(t * BB + b) * NT + n] = (unsigned char)apply;
        }
    }
}

// ================= k_back: label correction + feature correction ============
// blocks [0, NLC): labelcorr; [NLC, NLC+NFC): featcorr (2 tokens). 256 threads.
__global__ void __launch_bounds__(256) k_back(const int* __restrict__ slab,
                                              const float* __restrict__ tp,
                                              const float* __restrict__ alphas,
                                              float* __restrict__ out) {
    int tid = threadIdx.x;
    if (blockIdx.x < NLC) {
        int id = blockIdx.x;
        int chunk = id & 7;
        int yy = (id >> 3) % (KC * 16);
        int zz = id / (8 * KC * 16);
        int k = yy >> 4, pi = yy & 15;
        int b = zz >> 1, osel = zz & 1;   // 0=slc, 1=tlc
        __shared__ float seg[16][132];
        int sseg = tid >> 4, pj = tid & 15;
        for (int pass = 0; pass < 8; pass++) {
            int s = pass * 16 + sseg;
            int n = chunk * 128 + s;
            int aidx = (osel * BB + b) * NT + n;
            int apply = g_apply[aidx];
            int m = apply ? g_src[aidx] : n;
            int use_probs = (osel == 0) ? apply : !apply;
            int y = (m >> 5) * 16 + pi, x = (m & 31) * 16 + pj;
            float v;
            if (use_probs) v = tp[(((size_t)b * KC + k) * IMG + y) * IMG + x];
            else v = (slab[((size_t)b * IMG + y) * IMG + x] == k) ? 1.f : 0.f;
            seg[pj][s] = v;
        }
        __syncthreads();
        size_t obase = osel ? OFF_TLC : OFF_SLC;
#pragma unroll
        for (int it = 0; it < 2; it++) {
            int f = it * 256 + tid;
            int pjw = f >> 5, u = f & 31;
            float4 vv = *(const float4*)&seg[pjw][4 * u];
            size_t row = (size_t)b * (KC * PPX) + k * PPX + pi * 16 + pjw;
            __stcs((float4*)(out + obase + row * NT + chunk * 128) + u, vv);
        }
    } else {
        int fid = blockIdx.x - NLC;
        int n2 = fid & 511;
        int t = (fid >> 9) & 1;
        int b = fid >> 10;
        int sub = tid >> 7, c4 = tid & 127;
        int n = n2 * 2 + sub;
        float alpha = alphas[b];
        const float4* own = (const float4*)((t ? g_ttok : g_stok) + (size_t)b * NT * CF);
        const float4* oth = (const float4*)((t ? g_stok : g_ttok) + (size_t)b * NT * CF);
        float4 f = own[(size_t)n * 128 + c4];
        float4 r = f;
        int idx = (t * BB + b) * NT + n;
        if (g_apply[idx]) {
            float4 o = oth[(size_t)g_src[idx] * 128 + c4];
            float be = 1.f - alpha;
            r.x = alpha*f.x + be*o.x; r.y = alpha*f.y + be*o.y;
            r.z = alpha*f.z + be*o.z; r.w = alpha*f.w + be*o.w;
        } else if (!g_pure[t * BB * NT + b * NT + n] && g_both[b]) {
            float4 om = ((const float4*)(g_statmean + (b * 2 + t) * CF))[c4];
            float4 os = ((const float4*)(g_statstd  + (b * 2 + t) * CF))[c4];
            float4 xm = ((const float4*)(g_statmean + (b * 2 + (1 - t)) * CF))[c4];
            float4 xs = ((const float4*)(g_statstd  + (b * 2 + (1 - t)) * CF))[c4];
            float be = 1.f - alpha;
            float sx = (f.x - om.x) / (os.x + 1e-5f) * xs.x + xm.x;
            float sy = (f.y - om.y) / (os.y + 1e-5f) * xs.y + xm.y;
            float sz = (f.z - om.z) / (os.z + 1e-5f) * xs.z + xm.z;
            float sw = (f.w - om.w) / (os.w + 1e-5f) * xs.w + xm.w;
            r.x = alpha*f.x + be*sx; r.y = alpha*f.y + be*sy;
            r.z = alpha*f.z + be*sz; r.w = alpha*f.w + be*sw;
        }
        ((float4*)(out + (t ? OFF_TFC : OFF_SFC)))[((size_t)b * NT + n) * 128 + c4] = r;
        if (b == 0 && n < KC) {
            int bid = t * KC + n;
            ((float4*)(out + OFF_SP))[(size_t)bid * 128 + c4] =
                ((const float4*)g_proto)[bid * 128 + c4];
        }
    }
}

// ---------------- launch ----------------
extern "C" void kernel_launch(void* const* d_in, const int* in_sizes, int n_in,
                              void* d_out, int out_size) {
    const float* sfeat = nullptr; const float* tfeat = nullptr;
    const int* slab = nullptr; const float* tp = nullptr; const float* alphas = nullptr;
    for (int i = 0; i < n_in; i++) {
        int sz = in_sizes[i];
        if (sz == BB*CF*16*16) { if (!sfeat) sfeat = (const float*)d_in[i]; else tfeat = (const float*)d_in[i]; }
        else if (sz == BB*IMG*IMG) slab = (const int*)d_in[i];
        else if (sz == BB*KC*IMG*IMG) tp = (const float*)d_in[i];
        else if (sz == BB) alphas = (const float*)d_in[i];
    }
    float* out = (float*)d_out;

    k_front<<<2304, 256>>>(slab, tp, sfeat, tfeat);
    k_chain<<<NBLK, 1024>>>();
    k_back<<<NLC + NFC, 256>>>(slab, tp, alphas, out);
}

// round 8
// speedup vs baseline: 1.1646x; 1.1646x over previous
#include <cuda_runtime.h>
#include <cuda_bf16.h>
#include <math.h>

// ---------------- problem constants ----------------
#define BB   4
#define CF   512
#define KC   19
#define NT   1024            // tokens per image (32x32)
#define IMG  512
#define PPX  256             // patch pixels (16x16)
#define TK   (2*KC)          // 38
#define NBLK (BB*TK)         // 152 chain blocks

// output layout (floats): sfc, tfc, slc, tlc, s_proto, t_proto
#define SZ_FC    ((size_t)BB*NT*CF)
#define OFF_SFC  0ULL
#define OFF_TFC  (SZ_FC)
#define OFF_SLC  (2*SZ_FC)
#define SZ_LC    ((size_t)BB*KC*PPX*NT)
#define OFF_TLC  (OFF_SLC + SZ_LC)
#define OFF_SP   (OFF_TLC + SZ_LC)

// k_back block counts
#define NFC  ((NT/2) * 2 * BB)             // 4096 featcorr blocks (2 tokens each)
#define NLC  (8 * (KC*16) * (BB*2))        // 19456 labelcorr blocks

// ---------------- device scratch (static; no allocation) ----------------
__device__ float g_stok[BB*NT*CF];                 // [b][n][c]
__device__ float g_ttok[BB*NT*CF];
__device__ int           g_mode[2*BB*NT];          // [t][b][n]
__device__ unsigned char g_pure[2*BB*NT];
__device__ int   g_clist[BB*TK*NT];                // [b*TK + t*KC + k][i]
__device__ int   g_ccnt [BB*TK];
__device__ int   g_rank [BB*2*NT];
__device__ int   g_gate [BB*2];
__device__ int   g_impcnt[BB*2];
__device__ float g_mean [BB*TK*CF];
__device__ float g_proto[TK*CF];                   // final proto state
__device__ int   g_order[BB*TK*NT];
__device__ int           g_src  [2*BB*NT];
__device__ unsigned char g_apply[2*BB*NT];
__device__ float g_statmean[BB*2*CF];
__device__ float g_statstd [BB*2*CF];
__device__ int   g_both[BB];

// software grid barrier state
__device__ unsigned g_barGen = 0;
__device__ unsigned g_barCnt = 0;

__device__ __forceinline__ void grid_bar() {
    __threadfence();
    __syncthreads();
    if (threadIdx.x == 0) {
        unsigned my = *((volatile unsigned*)&g_barGen);
        unsigned a = atomicAdd(&g_barCnt, 1u);
        if (a == NBLK - 1) {
            atomicExch(&g_barCnt, 0u);
            __threadfence();
            atomicExch(&g_barGen, my + 1u);
        } else {
            while (*((volatile unsigned*)&g_barGen) == my) { __nanosleep(64); }
        }
        __threadfence();
    }
    __syncthreads();
}

// ================= k_front: upsample (first) + patch stats ==================
// blocks [0,256): upsample; [256, 2304): patch. 256 threads.
__global__ void __launch_bounds__(256) k_front(const int* __restrict__ slab,
                                               const float* __restrict__ tp,
                                               const float* __restrict__ sfeat,
                                               const float* __restrict__ tfeat) {
    int tid = threadIdx.x;
    if (blockIdx.x < 256) {
        // upsample: 2x bilinear (jax semantics); 2 channels per thread
        int u = blockIdx.x;
        int yo = u & 31;
        int b = (u >> 5) & 3;
        int t = u >> 7;
        const float* in = t ? tfeat : sfeat;
        float* dst = t ? g_ttok : g_stok;
        int k = yo >> 1; int r0, r1; float wy0, wy1;
        if (yo & 1) { r0 = k; r1 = (k < 15) ? k + 1 : 15; wy0 = 0.75f; wy1 = 0.25f; }
        else        { r0 = (k > 0) ? k - 1 : 0; r1 = k;   wy0 = 0.25f; wy1 = 0.75f; }
#pragma unroll
        for (int half = 0; half < 2; half++) {
            int c = tid + half * 256;
            const float4* base = (const float4*)(in + ((size_t)b * CF + c) * 256);
            float a0[16], a1[16];
#pragma unroll
            for (int q = 0; q < 4; q++) {
                float4 v0 = base[r0*4 + q], v1 = base[r1*4 + q];
                a0[q*4+0]=v0.x; a0[q*4+1]=v0.y; a0[q*4+2]=v0.z; a0[q*4+3]=v0.w;
                a1[q*4+0]=v1.x; a1[q*4+1]=v1.y; a1[q*4+2]=v1.z; a1[q*4+3]=v1.w;
            }
#pragma unroll
            for (int xo = 0; xo < 32; xo++) {
                int kx = xo >> 1; int x0, x1; float wx0, wx1;
                if (xo & 1) { x0 = kx; x1 = (kx < 15) ? kx + 1 : 15; wx0 = 0.75f; wx1 = 0.25f; }
                else        { x0 = (kx > 0) ? kx - 1 : 0; x1 = kx;   wx0 = 0.25f; wx1 = 0.75f; }
                float v0 = wy0 * a0[x0] + wy1 * a1[x0];
                float v1 = wy0 * a0[x1] + wy1 * a1[x1];
                dst[((size_t)b * NT + yo*32 + xo) * CF + c] = wx0 * v0 + wx1 * v1;
            }
        }
    } else {
        int id = blockIdx.x - 256;
        int z = id >> 10;            // 0 source, 1 target
        int rem = id & 1023;
        int b = rem >> 8;
        int px = rem & 255;          // patch group (4 patches)
        int p = tid >> 6, r = tid & 63;
        int pi = r >> 2, xq = r & 3;
        int n = px * 4 + p;
        int y = (n >> 5) * 16 + pi;
        int xb = (n & 31) * 16 + xq * 4;
        __shared__ int h[4][20];
        if (tid < 80) h[tid / 20][tid % 20] = 0;
        if (z == 0) {
            const int4* s4 = (const int4*)slab;
            int4 v = s4[((size_t)b * IMG + y) * (IMG/4) + (xb >> 2)];
            __syncthreads();
            atomicAdd(&h[p][v.x + 1], 1); atomicAdd(&h[p][v.y + 1], 1);
            atomicAdd(&h[p][v.z + 1], 1); atomicAdd(&h[p][v.w + 1], 1);
            __syncthreads();
            if (r == 0) {
                int best = -1, mj = 0;
                for (int j = 0; j < 20; j++) if (h[p][j] > best) { best = h[p][j]; mj = j; }
                int mode = mj - 1;
                int nvalid = 256 - h[p][0];
                int agree = (mode >= 0) ? h[p][mj] : 0;
                float purity = (float)agree / (float)(nvalid > 0 ? nvalid : 1);
                g_mode[b * NT + n] = mode;
                g_pure[b * NT + n] = (unsigned char)((purity >= 0.9f) && (nvalid > 0));
            }
        } else {
            const float4* tp4 = (const float4*)tp;
            size_t pix4 = (((size_t)b * KC) * IMG + y) * (IMG/4) + (xb >> 2);
            float mv0=-1.f, mv1=-1.f, mv2=-1.f, mv3=-1.f;
            int mk0=0, mk1=0, mk2=0, mk3=0;
#pragma unroll
            for (int k = 0; k < KC; k++) {
                float4 v = tp4[pix4 + (size_t)k * (IMG * (IMG/4))];
                if (v.x > mv0) { mv0 = v.x; mk0 = k; }
                if (v.y > mv1) { mv1 = v.y; mk1 = k; }
                if (v.z > mv2) { mv2 = v.z; mk2 = k; }
                if (v.w > mv3) { mv3 = v.w; mk3 = k; }
            }
            __shared__ float sc[256];
            sc[tid] = mv0 + mv1 + mv2 + mv3;
            __syncthreads();
            int l0 = (mv0 < 0.9f) ? 0 : mk0 + 1;
            int l1 = (mv1 < 0.9f) ? 0 : mk1 + 1;
            int l2 = (mv2 < 0.9f) ? 0 : mk2 + 1;
            int l3 = (mv3 < 0.9f) ? 0 : mk3 + 1;
            atomicAdd(&h[p][l0], 1); atomicAdd(&h[p][l1], 1);
            atomicAdd(&h[p][l2], 1); atomicAdd(&h[p][l3], 1);
            __syncthreads();
            for (int s = 32; s > 0; s >>= 1) {
                if (r < s) sc[tid] += sc[tid + s];
                __syncthreads();
            }
            if (r == 0) {
                float cmean = sc[p * 64] / 256.f;
                int best = -1, mj = 0;
                for (int j = 0; j < 20; j++) if (h[p][j] > best) { best = h[p][j]; mj = j; }
                int mode = mj - 1;
                int nvalid = 256 - h[p][0];
                int agree = (mode >= 0) ? h[p][mj] : 0;
                float purity = (float)agree / (float)(nvalid > 0 ? nvalid : 1);
                int pure = (purity >= 0.9f) && (nvalid > 0) && (cmean >= 0.9f);
                g_mode[BB*NT + b * NT + n] = mode;
                g_pure[BB*NT + b * NT + n] = (unsigned char)pure;
            }
        }
    }
}

// ===== k_chain: 152 blocks x 512 thr; prep -> means -> EMA+dist+sort -> match
__global__ void __launch_bounds__(512, 2) k_chain() {
    __shared__ int    lst[NT];
    __shared__ float  ds[NT];
    __shared__ float4 pr4[128];
    __shared__ float4 part4[4][128];
    __shared__ int    simp0[NT];
    __shared__ int    s_impcnt;
    __shared__ float4 smean1[128];
    int tid = threadIdx.x;
    int w = tid >> 5, lane = tid & 31;

    // -------- phase A: blocks 0..7 = (b,t): lists, ranks, gates, impure stats
    if (blockIdx.x < 2 * BB) {
        int b = blockIdx.x >> 1, t = blockIdx.x & 1;
        const int* md = g_mode + t * BB * NT + b * NT;
        const unsigned char* pu = g_pure + t * BB * NT + b * NT;
        for (int item = w; item < 20; item += 16) {
            if (item < KC) {
                int k = item;
                int cnt = 0;
                for (int base = 0; base < NT; base += 32) {
                    int n = base + lane;
                    bool mem = pu[n] && (md[n] == k);
                    unsigned m = __ballot_sync(0xffffffffu, mem);
                    int pos = cnt + __popc(m & ((1u << lane) - 1u));
                    if (mem) {
                        g_clist[(b*TK + t*KC + k)*NT + pos] = n;
                        g_rank[(b*2+t)*NT + n] = pos;
                    }
                    cnt += __popc(m);
                }
                if (lane == 0) g_ccnt[b*TK + t*KC + k] = cnt;
            } else {
                int cnt = 0;
                for (int base = 0; base < NT; base += 32) {
                    int n = base + lane;
                    bool mem = !pu[n];
                    unsigned m = __ballot_sync(0xffffffffu, mem);
                    int pos = cnt + __popc(m & ((1u << lane) - 1u));
                    if (mem) simp0[pos] = n;
                    cnt += __popc(m);
                }
                if (lane == 0) s_impcnt = cnt;
            }
        }
        __syncthreads();
        if (tid == 0) {
            int s = 0;
            for (int k = 0; k < KC; k++) s += g_ccnt[b*TK + t*KC + k];
            g_gate[b*2+t] = (s > 0);
            g_impcnt[b*2+t] = s_impcnt;
        }
        // impure stats: 4 member-lanes x 128 c4
        int l = tid >> 7, c4 = tid & 127;
        int n = s_impcnt;
        const float4* f4 = (const float4*)((t ? g_ttok : g_stok) + (size_t)b * NT * CF);
        float4 a = make_float4(0.f, 0.f, 0.f, 0.f);
        int i = l;
        for (; i + 4 < n; i += 8) {
            float4 v0 = f4[(size_t)simp0[i    ] * 128 + c4];
            float4 v1 = f4[(size_t)simp0[i + 4] * 128 + c4];
            a.x += v0.x + v1.x; a.y += v0.y + v1.y; a.z += v0.z + v1.z; a.w += v0.w + v1.w;
        }
        for (; i < n; i += 4) {
            float4 v = f4[(size_t)simp0[i] * 128 + c4];
            a.x += v.x; a.y += v.y; a.z += v.z; a.w += v.w;
        }
        part4[l][c4] = a;
        __syncthreads();
        if (tid < 128) {
            float4 s0 = part4[0][tid], s1 = part4[1][tid];
            float4 s2 = part4[2][tid], s3 = part4[3][tid];
            float inv = 1.f / (float)(n > 0 ? n : 1);
            float4 mn;
            mn.x = (s0.x + s1.x + s2.x + s3.x) * inv;
            mn.y = (s0.y + s1.y + s2.y + s3.y) * inv;
            mn.z = (s0.z + s1.z + s2.z + s3.z) * inv;
            mn.w = (s0.w + s1.w + s2.w + s3.w) * inv;
            ((float4*)(g_statmean + (b * 2 + t) * CF))[tid] = mn;
            smean1[tid] = mn;
        }
        __syncthreads();
        float4 mn = smean1[c4];
        float4 q = make_float4(0.f, 0.f, 0.f, 0.f);
        for (i = l; i < n; i += 4) {
            float4 v = f4[(size_t)simp0[i] * 128 + c4];
            float dx = v.x - mn.x, dy = v.y - mn.y, dz = v.z - mn.z, dw = v.w - mn.w;
            q.x += dx*dx; q.y += dy*dy; q.z += dz*dz; q.w += dw*dw;
        }
        part4[l][c4] = q;
        __syncthreads();
        if (tid < 128) {
            float4 s0 = part4[0][tid], s1 = part4[1][tid];
            float4 s2 = part4[2][tid], s3 = part4[3][tid];
            float invv = 1.f / (float)(n - 1 > 0 ? n - 1 : 1);
            float4 sd;
            sd.x = (n > 1) ? sqrtf((s0.x + s1.x + s2.x + s3.x) * invv) : 0.f;
            sd.y = (n > 1) ? sqrtf((s0.y + s1.y + s2.y + s3.y) * invv) : 0.f;
            sd.z = (n > 1) ? sqrtf((s0.z + s1.z + s2.z + s3.z) * invv) : 0.f;
            sd.w = (n > 1) ? sqrtf((s0.w + s1.w + s2.w + s3.w) * invv) : 0.f;
            ((float4*)(g_statstd + (b * 2 + t) * CF))[tid] = sd;
        }
    }
    grid_bar();

    // -------- phase B1: per (b,class) means (all 152 blocks parallel) -------
    int g = blockIdx.x;
    int b = g / TK, bid = g % TK;
    int t = bid / KC, k = bid - t * KC;
    {
        if (bid == 0 && tid == 0)
            g_both[b] = (__ldcg(&g_impcnt[b*2]) > 0) && (__ldcg(&g_impcnt[b*2+1]) > 0);
        int cnt = __ldcg(&g_ccnt[g]);
        for (int i = tid; i < cnt; i += 512) lst[i] = __ldcg(&g_clist[g*NT + i]);
        __syncthreads();
        int l = tid >> 7, c4 = tid & 127;
        const float4* fb = (const float4*)((t ? g_ttok : g_stok) + (size_t)b * NT * CF);
        float4 a = make_float4(0.f, 0.f, 0.f, 0.f);
        int i = l;
        for (; i + 4 < cnt; i += 8) {
            float4 v0 = fb[(size_t)lst[i    ] * 128 + c4];
            float4 v1 = fb[(size_t)lst[i + 4] * 128 + c4];
            a.x += v0.x + v1.x; a.y += v0.y + v1.y; a.z += v0.z + v1.z; a.w += v0.w + v1.w;
        }
        for (; i < cnt; i += 4) {
            float4 v = fb[(size_t)lst[i] * 128 + c4];
            a.x += v.x; a.y += v.y; a.z += v.z; a.w += v.w;
        }
        part4[l][c4] = a;
        __syncthreads();
        if (tid < 128) {
            float4 s0 = part4[0][tid], s1 = part4[1][tid];
            float4 s2 = part4[2][tid], s3 = part4[3][tid];
            float inv = 1.f / (float)(cnt > 0 ? cnt : 1);
            float4 s;
            s.x = (s0.x + s1.x + s2.x + s3.x) * inv;
            s.y = (s0.y + s1.y + s2.y + s3.y) * inv;
            s.z = (s0.z + s1.z + s2.z + s3.z) * inv;
            s.w = (s0.w + s1.w + s2.w + s3.w) * inv;
            ((float4*)(g_mean + (size_t)g * CF))[tid] = s;
        }
    }
    grid_bar();

    // -------- phase B2: EMA proto + member dist + stable sort ---------------
    {
        int cnt = __ldcg(&g_ccnt[g]);
        if (tid < 128) {
            float4 pv = make_float4(0.f, 0.f, 0.f, 0.f);
#pragma unroll
            for (int bb = 0; bb < BB; bb++) {
                if (bb > b) break;
                int cbb = __ldcg(&g_ccnt[bb*TK + bid]);
                int gate = t ? (__ldcg(&g_gate[bb*2]) && __ldcg(&g_gate[bb*2+1]))
                             : __ldcg(&g_gate[bb*2]);
                if (gate && cbb > 0) {
                    float4 mv;
                    const float4* mp = (const float4*)(g_mean + (size_t)(bb*TK + bid) * CF);
                    mv.x = __ldcg(&((const float*)&mp[tid])[0]);
                    mv.y = __ldcg(&((const float*)&mp[tid])[1]);
                    mv.z = __ldcg(&((const float*)&mp[tid])[2]);
                    mv.w = __ldcg(&((const float*)&mp[tid])[3]);
                    pv.x = 0.99f*pv.x + 0.01f*mv.x; pv.y = 0.99f*pv.y + 0.01f*mv.y;
                    pv.z = 0.99f*pv.z + 0.01f*mv.z; pv.w = 0.99f*pv.w + 0.01f*mv.w;
                }
            }
            pr4[tid] = pv;
            if (b == BB - 1) ((float4*)g_proto)[bid * 128 + tid] = pv;
        }
        __syncthreads();
        const float4* fb = (const float4*)((t ? g_ttok : g_stok) + (size_t)b * NT * CF);
        for (int mi = w; mi < cnt; mi += 16) {
            const float4* fv = fb + (size_t)lst[mi] * 128;
            float acc = 0.f;
#pragma unroll
            for (int q = 0; q < 4; q++) {
                int e = lane + q * 32;
                float4 v = fv[e];
                float4 p = pr4[e];
                float d0 = v.x - p.x, d1 = v.y - p.y, d2 = v.z - p.z, d3 = v.w - p.w;
                acc += d0*d0 + d1*d1 + d2*d2 + d3*d3;
            }
            for (int o = 16; o; o >>= 1) acc += __shfl_down_sync(0xffffffffu, acc, o);
            if (lane == 0) ds[mi] = sqrtf(acc);
        }
        __syncthreads();
        for (int i = tid; i < cnt; i += 512) {
            float di = ds[i]; int r = 0;
            for (int j = 0; j < cnt; j++) {
                float dj = ds[j];
                r += (dj < di) || (dj == di && j < i);
            }
            g_order[g * NT + r] = lst[i];
        }
    }
    grid_bar();

    // -------- phase C: cyclic source matching -------------------------------
    {
        int id = blockIdx.x * 512 + tid;
        if (id < 2 * BB * NT) {
            int bb = id >> 11;
            int rem = id & 2047;
            int tt = rem >> 10;
            int n = rem & 1023;
            int gate_st = __ldcg(&g_gate[bb*2]) && __ldcg(&g_gate[bb*2+1]);
            int mode = g_mode[tt * BB * NT + bb * NT + n];
            int pure = g_pure[tt * BB * NT + bb * NT + n];
            int cm = mode > 0 ? mode : 0;
            int cs = __ldcg(&g_ccnt[bb*TK + (1 - tt) * KC + cm]);
            int apply = pure && (cs > 0) && gate_st;
            int src = 0;
            if (apply) {
                int r = __ldcg(&g_rank[(bb*2 + tt) * NT + n]);
                src = __ldcg(&g_order[(bb*TK + (1 - tt) * KC + cm) * NT + (r % cs)]);
            }
            g_src  [(tt * BB + bb) * NT + n] = src;
            g_apply[(tt * BB + bb) * NT + n] = (unsigned char)apply;
        }
    }
}

// ================= k_back: featcorr (first) + label correction ==============
__global__ void __launch_bounds__(256) k_back(const int* __restrict__ slab,
                                              const float* __restrict__ tp,
                                              const float* __restrict__ alphas,
                                              float* __restrict__ out) {
    int tid = threadIdx.x;
    if (blockIdx.x < NFC) {
        int fid = blockIdx.x;
        int n2 = fid & 511;
        int t = (fid >> 9) & 1;
        int b = fid >> 10;
        int sub = tid >> 7, c4 = tid & 127;
        int n = n2 * 2 + sub;
        float alpha = alphas[b];
        const float4* own = (const float4*)((t ? g_ttok : g_stok) + (size_t)b * NT * CF);
        const float4* oth = (const float4*)((t ? g_stok : g_ttok) + (size_t)b * NT * CF);
        float4 f = own[(size_t)n * 128 + c4];
        float4 r = f;
        int idx = (t * BB + b) * NT + n;
        if (g_apply[idx]) {
            float4 o = oth[(size_t)g_src[idx] * 128 + c4];
            float be = 1.f - alpha;
            r.x = alpha*f.x + be*o.x; r.y = alpha*f.y + be*o.y;
            r.z = alpha*f.z + be*o.z; r.w = alpha*f.w + be*o.w;
        } else if (!g_pure[t * BB * NT + b * NT + n] && g_both[b]) {
            float4 om = ((const float4*)(g_statmean + (b * 2 + t) * CF))[c4];
            float4 os = ((const float4*)(g_statstd  + (b * 2 + t) * CF))[c4];
            float4 xm = ((const float4*)(g_statmean + (b * 2 + (1 - t)) * CF))[c4];
            float4 xs = ((const float4*)(g_statstd  + (b * 2 + (1 - t)) * CF))[c4];
            float be = 1.f - alpha;
            float sx = (f.x - om.x) / (os.x + 1e-5f) * xs.x + xm.x;
            float sy = (f.y - om.y) / (os.y + 1e-5f) * xs.y + xm.y;
            float sz = (f.z - om.z) / (os.z + 1e-5f) * xs.z + xm.z;
            float sw = (f.w - om.w) / (os.w + 1e-5f) * xs.w + xm.w;
            r.x = alpha*f.x + be*sx; r.y = alpha*f.y + be*sy;
            r.z = alpha*f.z + be*sz; r.w = alpha*f.w + be*sw;
        }
        ((float4*)(out + (t ? OFF_TFC : OFF_SFC)))[((size_t)b * NT + n) * 128 + c4] = r;
        if (b == 0 && n < KC) {
            int bid = t * KC + n;
            ((float4*)(out + OFF_SP))[(size_t)bid * 128 + c4] =
                ((const float4*)g_proto)[bid * 128 + c4];
        }
    } else {
        int id = blockIdx.x - NFC;
        int chunk = id & 7;
        int yy = (id >> 3) % (KC * 16);
        int zz = id / (8 * KC * 16);
        int k = yy >> 4, pi = yy & 15;
        int b = zz >> 1, osel = zz & 1;   // 0=slc, 1=tlc
        __shared__ float seg[16][132];
        int sseg = tid >> 4, pj = tid & 15;
        for (int pass = 0; pass < 8; pass++) {
            int s = pass * 16 + sseg;
            int n = chunk * 128 + s;
            int aidx = (osel * BB + b) * NT + n;
            int apply = g_apply[aidx];
            int m = apply ? g_src[aidx] : n;
            int use_probs = (osel == 0) ? apply : !apply;
            int y = (m >> 5) * 16 + pi, x = (m & 31) * 16 + pj;
            float v;
            if (use_probs) v = tp[(((size_t)b * KC + k) * IMG + y) * IMG + x];
            else v = (slab[((size_t)b * IMG + y) * IMG + x] == k) ? 1.f : 0.f;
            seg[pj][s] = v;
        }
        __syncthreads();
        size_t obase = osel ? OFF_TLC : OFF_SLC;
#pragma unroll
        for (int it = 0; it < 2; it++) {
            int f = it * 256 + tid;
            int pjw = f >> 5, u = f & 31;
            float4 vv = *(const float4*)&seg[pjw][4 * u];
            size_t row = (size_t)b * (KC * PPX) + k * PPX + pi * 16 + pjw;
            __stcs((float4*)(out + obase + row * NT + chunk * 128) + u, vv);
        }
    }
}

// ---------------- launch ----------------
extern "C" void kernel_launch(void* const* d_in, const int* in_sizes, int n_in,
                              void* d_out, int out_size) {
    const float* sfeat = nullptr; const float* tfeat = nullptr;
    const int* slab = nullptr; const float* tp = nullptr; const float* alphas = nullptr;
    for (int i = 0; i < n_in; i++) {
        int sz = in_sizes[i];
        if (sz == BB*CF*16*16) { if (!sfeat) sfeat = (const float*)d_in[i]; else tfeat = (const float*)d_in[i]; }
        else if (sz == BB*IMG*IMG) slab = (const int*)d_in[i];
        else if (sz == BB*KC*IMG*IMG) tp = (const float*)d_in[i];
        else if (sz == BB) alphas = (const float*)d_in[i];
    }
    float* out = (float*)d_out;

    k_front<<<2304, 256>>>(slab, tp, sfeat, tfeat);
    k_chain<<<NBLK, 512>>>();
    k_back<<<NFC + NLC, 256>>>(slab, tp, alphas, out);
}